// round 5
// baseline (speedup 1.0000x reference)
#include <cuda_runtime.h>

// Gaussian splatting via tile-owned gather (no global atomics).
// K1: zero per-tile counters. K2: per-gaussian param prep + bucket scatter
// (tile = 16^3, bbox <= 14 so <= 8 tiles/gaussian). K3: one CTA per tile,
// thread owns an (x,y) column of 16 z-voxels in registers; gaussians
// processed in batches of 8 with smem exp tables (clipped entries = 0);
// volume written exactly once with coalesced float4 stores.

#define NT 16
#define NTILES (NT * NT * NT)          // 4096
#define CAP 192
#define NMAX 65536

__device__ int    d_counts[NTILES];
__device__ int    d_bucket[NTILES * CAP];
__device__ float4 d_params[2 * NMAX];  // [2g] = {cx,cy,cz,inv2s2}; [2g+1] = {I, mnPack, mxm1Pack, 0}

__global__ void zero_kernel() {
    int i = blockIdx.x * blockDim.x + threadIdx.x;
    if (i < NTILES) d_counts[i] = 0;
}

__global__ void scatter_kernel(const float* __restrict__ centers,
                               const float* __restrict__ sigmas,
                               const float* __restrict__ intensities,
                               int n) {
    int g = blockIdx.x * blockDim.x + threadIdx.x;
    if (g >= n) return;

    float c3[3];
    c3[0] = __ldg(&centers[3 * g + 0]);
    c3[1] = __ldg(&centers[3 * g + 1]);
    c3[2] = __ldg(&centers[3 * g + 2]);
    const float sig   = __ldg(&sigmas[g]);
    const float inten = __ldg(&intensities[g]);

    const float cut    = 3.0f * sig * 255.0f;
    const float inv2s2 = 0.5f / (sig * sig);

    int mn[3], mx[3];
#pragma unroll
    for (int a = 0; a < 3; a++) {
        float cv = c3[a] * 255.0f;
        mn[a] = (int)floorf(fmaxf(cv - cut, 0.0f));
        mx[a] = (int)fminf(floorf(fminf(cv + cut, 255.0f)) + 1.0f, 256.0f);
    }

    unsigned mnp  = (unsigned)mn[0] | ((unsigned)mn[1] << 8) | ((unsigned)mn[2] << 16);
    unsigned mxp  = (unsigned)(mx[0] - 1) | ((unsigned)(mx[1] - 1) << 8) | ((unsigned)(mx[2] - 1) << 16);

    float4 p0 = make_float4(c3[0], c3[1], c3[2], inv2s2);
    float4 p1 = make_float4(inten, __uint_as_float(mnp), __uint_as_float(mxp), 0.0f);
    d_params[2 * g + 0] = p0;
    d_params[2 * g + 1] = p1;

    const int t0x = mn[0] >> 4, t1x = (mx[0] - 1) >> 4;
    const int t0y = mn[1] >> 4, t1y = (mx[1] - 1) >> 4;
    const int t0z = mn[2] >> 4, t1z = (mx[2] - 1) >> 4;

    for (int tx = t0x; tx <= t1x; tx++)
        for (int ty = t0y; ty <= t1y; ty++)
            for (int tz = t0z; tz <= t1z; tz++) {
                int t = (tx << 8) | (ty << 4) | tz;
                int slot = atomicAdd(&d_counts[t], 1);
                if (slot < CAP) d_bucket[t * CAP + slot] = g;
            }
}

__global__ void __launch_bounds__(256) accum_kernel(float* __restrict__ out) {
    const int t   = blockIdx.x;
    const int tid = threadIdx.x;
    const int ox = ((t >> 8) & 15) << 4;
    const int oy = ((t >> 4) & 15) << 4;
    const int oz = (t & 15) << 4;

    __shared__ float4 sh_par[8][2];
    __shared__ float  sh_tab[8][3][16];
    __shared__ float  sh_stage[16 * 256];   // z-major: [z*256 + col]

    int cnt = d_counts[t];
    if (cnt > CAP) cnt = CAP;

    float acc[16];
#pragma unroll
    for (int z = 0; z < 16; z++) acc[z] = 0.0f;

    const int xi = tid >> 4;   // column x within tile
    const int yi = tid & 15;   // column y within tile

    for (int b = 0; b < cnt; b += 8) {
        const int G = min(8, cnt - b);
        __syncthreads();  // previous batch's accumulate done before smem reuse
        if (tid < 2 * G) {
            int g = tid >> 1, half = tid & 1;
            int gid = d_bucket[t * CAP + b + g];
            sh_par[g][half] = d_params[2 * gid + half];
        }
        __syncthreads();

        // Build clipped exp tables: 48 entries per gaussian; zeros outside bbox.
        for (int e = tid; e < 48 * G; e += 256) {
            int g = e / 48;
            int r = e - g * 48;
            int a = r >> 4, i = r & 15;
            const float* p0 = (const float*)&sh_par[g][0];
            float  c      = p0[a];
            float  inv2s2 = p0[3];
            float4 p1     = sh_par[g][1];
            unsigned mnp = __float_as_uint(p1.y);
            unsigned mxp = __float_as_uint(p1.z);
            int mn_a = (int)((mnp >> (8 * a)) & 255u);
            int mx_a = (int)((mxp >> (8 * a)) & 255u) + 1;   // exclusive
            int o = (a == 0) ? ox : ((a == 1) ? oy : oz);
            int gi = o + i;
            float v = 0.0f;
            if (gi >= mn_a && gi < mx_a) {
                float d = (float)gi / 255.0f - c;
                v = expf(-d * d * inv2s2);
                if (a == 2) v *= p1.x;
            }
            sh_tab[g][a][i] = v;
        }
        __syncthreads();

        // Accumulate batch into registers.
        for (int g = 0; g < G; g++) {
            float exy = sh_tab[g][0][xi] * sh_tab[g][1][yi];
            if (exy != 0.0f) {
                const float4* ez = (const float4*)sh_tab[g][2];
                float4 e0 = ez[0], e1 = ez[1], e2 = ez[2], e3 = ez[3];
                acc[0]  = fmaf(exy, e0.x, acc[0]);
                acc[1]  = fmaf(exy, e0.y, acc[1]);
                acc[2]  = fmaf(exy, e0.z, acc[2]);
                acc[3]  = fmaf(exy, e0.w, acc[3]);
                acc[4]  = fmaf(exy, e1.x, acc[4]);
                acc[5]  = fmaf(exy, e1.y, acc[5]);
                acc[6]  = fmaf(exy, e1.z, acc[6]);
                acc[7]  = fmaf(exy, e1.w, acc[7]);
                acc[8]  = fmaf(exy, e2.x, acc[8]);
                acc[9]  = fmaf(exy, e2.y, acc[9]);
                acc[10] = fmaf(exy, e2.z, acc[10]);
                acc[11] = fmaf(exy, e2.w, acc[11]);
                acc[12] = fmaf(exy, e3.x, acc[12]);
                acc[13] = fmaf(exy, e3.y, acc[13]);
                acc[14] = fmaf(exy, e3.z, acc[14]);
                acc[15] = fmaf(exy, e3.w, acc[15]);
            }
        }
    }

    // Transposed writeout through smem for coalesced float4 stores.
    __syncthreads();
#pragma unroll
    for (int z = 0; z < 16; z++) sh_stage[z * 256 + tid] = acc[z];
    __syncthreads();

#pragma unroll
    for (int s = 0; s < 4; s++) {
        int idx = s * 256 + tid;     // float4 index within tile (0..1023)
        int f   = idx << 2;          // flat float index: col*16 + z
        int c   = f >> 4;            // column 0..255
        int z0  = f & 15;            // 0,4,8,12
        float4 v;
        v.x = sh_stage[(z0 + 0) * 256 + c];
        v.y = sh_stage[(z0 + 1) * 256 + c];
        v.z = sh_stage[(z0 + 2) * 256 + c];
        v.w = sh_stage[(z0 + 3) * 256 + c];
        int addr = (ox + (c >> 4)) * 65536 + (oy + (c & 15)) * 256 + oz + z0;
        *(float4*)&out[addr] = v;
    }
}

extern "C" void kernel_launch(void* const* d_in, const int* in_sizes, int n_in,
                              void* d_out, int out_size) {
    const float* centers = (const float*)d_in[0];
    const float* sigmas = (const float*)d_in[1];
    const float* intensities = (const float*)d_in[2];
    float* out = (float*)d_out;
    const int n = in_sizes[1];

    zero_kernel<<<(NTILES + 255) / 256, 256>>>();
    scatter_kernel<<<(n + 255) / 256, 256>>>(centers, sigmas, intensities, n);
    accum_kernel<<<NTILES, 256>>>(out);
}